// round 4
// baseline (speedup 1.0000x reference)
#include <cuda_runtime.h>
#include <math.h>

#define STATW 162
#define OFF1  0
#define OFFS1 8
#define OFFS2 10
#define OFF2  18
#define OFF3  34
#define OFF4  66
#define OFF5  130

// ----------------- device scratch -----------------
__device__ float g_h1[33554432];   // conv1 raw (128,4,256,256); reused for sa2 raw
__device__ float g_x1[33554432];   // x*att
__device__ float g_s1[8388608];    // sa1 raw (128,1,256,256)
__device__ float g_p1[8388608];    // gated+pooled (128,4,128,128)
__device__ float g_c2[4194304];    // conv2 raw (128,8,64,64)
__device__ float g_p2[1048576];    // (128,8,32,32)
__device__ float g_c3[2097152];    // conv3 raw (128,16,32,32)
__device__ float g_p3[524288];     // (128,16,16,16)
__device__ float g_c4[1048576];    // conv4 raw (128,32,16,16)
__device__ float g_c5[524288];     // conv5 raw (128,16,16,16)
__device__ float g_pool[2048];     // (128,16)
__device__ float g_buckets[64*STATW];
__device__ float g_mi[STATW];      // mean/istd pairs

// ----------------- helpers -----------------
__device__ __forceinline__ void warp_stat(float s, float q, float* dst){
#pragma unroll
    for (int o=16;o>0;o>>=1){ s+=__shfl_down_sync(0xffffffffu,s,o); q+=__shfl_down_sync(0xffffffffu,q,o); }
    if ((threadIdx.x&31)==0){ atomicAdd(dst,s); atomicAdd(dst+1,q); }
}
__device__ __forceinline__ void flush_stats(const float* sh, int twoC, int off, int bucket){
    for (int i=threadIdx.x;i<twoC;i+=blockDim.x) atomicAdd(&g_buckets[bucket*STATW+off+i], sh[i]);
}

__global__ void k_zero(){ int i=blockIdx.x*256+threadIdx.x; if(i<64*STATW) g_buckets[i]=0.f; }

__global__ void k_fin(int off,int C,float invN){
    int c=threadIdx.x;
    if(c<C){
        float s=0.f,q=0.f;
        for(int k=0;k<64;k++){ s+=g_buckets[k*STATW+off+2*c]; q+=g_buckets[k*STATW+off+2*c+1]; }
        float m=s*invN; float v=q*invN-m*m;
        g_mi[off+2*c]=m; g_mi[off+2*c+1]=rsqrtf(v+1e-5f);
    }
}

// ----------------- conv1: 1->4, 5x5, s2, p2 (zero) -----------------
__global__ void k_conv1(const float* __restrict__ x, const float* __restrict__ w){
    __shared__ float tile[36*132];
    __shared__ float ws[100];
    __shared__ float sstat[8];
    int tid=threadIdx.x;
    int bx=blockIdx.x, by=blockIdx.y, b=blockIdx.z;
    if (tid<100) ws[tid]=w[tid];
    if (tid<8) sstat[tid]=0.f;
    const float* xin = x + (size_t)b*262144;
    int iy0=by*32-2, ix0=bx*128-2;
    for (int i=tid;i<36*132;i+=256){
        int r=i/132, c=i-r*132;
        int gy=iy0+r, gx=ix0+c;
        float v=0.f;
        if ((unsigned)gy<512u && (unsigned)gx<512u) v=xin[gy*512+gx];
        tile[i]=v;
    }
    __syncthreads();
    int ty=tid>>4, txg=tid&15;
    float acc[4][4];
#pragma unroll
    for(int c=0;c<4;c++)
#pragma unroll
        for(int p=0;p<4;p++) acc[c][p]=0.f;
#pragma unroll
    for(int ky=0;ky<5;ky++){
        const float* row=&tile[(2*ty+ky)*132 + 8*txg];
        float r[12];
#pragma unroll
        for(int j=0;j<12;j++) r[j]=row[j];
#pragma unroll
        for(int kx=0;kx<5;kx++){
#pragma unroll
            for(int c=0;c<4;c++){
                float wv=ws[c*25+ky*5+kx];
#pragma unroll
                for(int p=0;p<4;p++) acc[c][p]+=r[2*p+kx]*wv;
            }
        }
    }
    int oy=by*16+ty, ox0=bx*64+txg*4;
#pragma unroll
    for(int c=0;c<4;c++)
        *(float4*)&g_h1[((b*4+c)<<16)+oy*256+ox0]=make_float4(acc[c][0],acc[c][1],acc[c][2],acc[c][3]);
#pragma unroll
    for(int c=0;c<4;c++){
        float s=acc[c][0]+acc[c][1]+acc[c][2]+acc[c][3];
        float q=acc[c][0]*acc[c][0]+acc[c][1]*acc[c][1]+acc[c][2]*acc[c][2]+acc[c][3]*acc[c][3];
        warp_stat(s,q,&sstat[2*c]);
    }
    __syncthreads();
    int bucket=((blockIdx.z*gridDim.y+blockIdx.y)*gridDim.x+blockIdx.x)&63;
    flush_stats(sstat,8,OFF1,bucket);
}

// ----------------- bn1+relu + channel attention -----------------
__global__ void k_ca(const float* __restrict__ w1,const float* __restrict__ b1,
                     const float* __restrict__ w2,const float* __restrict__ b2){
    int g=blockIdx.x*256+threadIdx.x;   // 2,097,152 groups of 4 px
    int b=g>>14, q=g&16383;
    float m[4], is[4], W1[4], W2[4], B2[4];
#pragma unroll
    for(int c=0;c<4;c++){ m[c]=g_mi[OFF1+2*c]; is[c]=g_mi[OFF1+2*c+1]; W1[c]=w1[c]; W2[c]=w2[c]; B2[c]=b2[c]; }
    float B1=b1[0];
    float y[4][4];
#pragma unroll
    for(int c=0;c<4;c++){
        float4 v=*(const float4*)&g_h1[((b*4+c)<<16)+q*4];
        float* vp=(float*)&v;
#pragma unroll
        for(int j=0;j<4;j++) y[c][j]=fmaxf(0.f,(vp[j]-m[c])*is[c]);
    }
    float s[4];
#pragma unroll
    for(int j=0;j<4;j++){
        float a=B1;
#pragma unroll
        for(int c=0;c<4;c++) a+=y[c][j]*W1[c];
        s[j]=fmaxf(0.f,a);
    }
#pragma unroll
    for(int c=0;c<4;c++){
        float4 o; float* op=(float*)&o;
#pragma unroll
        for(int j=0;j<4;j++) op[j]=y[c][j]*(s[j]*W2[c]+B2[c]);
        *(float4*)&g_x1[((b*4+c)<<16)+q*4]=o;
    }
}

// ----------------- sa conv1: x1(4ch)->s1(1ch), 7x7, edge pad -----------------
__global__ void k_sa1(const float* __restrict__ w){
    __shared__ float tile[4*1540];   // 4ch x 22 x 70
    __shared__ float ws[196];
    __shared__ float sstat[2];
    int tid=threadIdx.x;
    int bx=blockIdx.x, by=blockIdx.y, b=blockIdx.z;
    if(tid<196) ws[tid]=w[tid];
    if(tid<2) sstat[tid]=0.f;
    int iy0=by*16-3, ix0=bx*64-3;
    for(int i=tid;i<6160;i+=256){
        int c=i/1540, j=i-c*1540;
        int r=j/70, cc=j-r*70;
        int gy=min(max(iy0+r,0),255), gx=min(max(ix0+cc,0),255);
        tile[i]=g_x1[((b*4+c)<<16)+gy*256+gx];
    }
    __syncthreads();
    int ty=tid>>4, txg=tid&15;
    float acc[4]={0.f,0.f,0.f,0.f};
    for(int c=0;c<4;c++){
#pragma unroll
        for(int ky=0;ky<7;ky++){
            const float* row=&tile[c*1540+(ty+ky)*70+txg*4];
            float r[10];
#pragma unroll
            for(int j=0;j<10;j++) r[j]=row[j];
#pragma unroll
            for(int kx=0;kx<7;kx++){
                float wv=ws[c*49+ky*7+kx];
#pragma unroll
                for(int p=0;p<4;p++) acc[p]+=r[p+kx]*wv;
            }
        }
    }
    int oy=by*16+ty, ox0=bx*64+txg*4;
    *(float4*)&g_s1[(b<<16)+oy*256+ox0]=make_float4(acc[0],acc[1],acc[2],acc[3]);
    float s=acc[0]+acc[1]+acc[2]+acc[3];
    float q=acc[0]*acc[0]+acc[1]*acc[1]+acc[2]*acc[2]+acc[3]*acc[3];
    warp_stat(s,q,&sstat[0]);
    __syncthreads();
    int bucket=((blockIdx.z*gridDim.y+blockIdx.y)*gridDim.x+blockIdx.x)&63;
    flush_stats(sstat,2,OFFS1,bucket);
}

// ----------------- sa conv2: relu(bn(s1)) -> 4ch raw (into g_h1), 7x7 edge -----------------
__global__ void k_sa2(const float* __restrict__ w){
    __shared__ float tile[1540];
    __shared__ float ws[196];
    __shared__ float sstat[8];
    int tid=threadIdx.x;
    int bx=blockIdx.x, by=blockIdx.y, b=blockIdx.z;
    if(tid<196) ws[tid]=w[tid];
    if(tid<8) sstat[tid]=0.f;
    float mS=g_mi[OFFS1], iS=g_mi[OFFS1+1];
    int iy0=by*16-3, ix0=bx*64-3;
    for(int i=tid;i<1540;i+=256){
        int r=i/70, cc=i-r*70;
        int gy=min(max(iy0+r,0),255), gx=min(max(ix0+cc,0),255);
        float v=g_s1[(b<<16)+gy*256+gx];
        tile[i]=fmaxf(0.f,(v-mS)*iS);
    }
    __syncthreads();
    int ty=tid>>4, txg=tid&15;
    float acc[4][4];
#pragma unroll
    for(int c=0;c<4;c++)
#pragma unroll
        for(int p=0;p<4;p++) acc[c][p]=0.f;
#pragma unroll
    for(int ky=0;ky<7;ky++){
        const float* row=&tile[(ty+ky)*70+txg*4];
        float r[10];
#pragma unroll
        for(int j=0;j<10;j++) r[j]=row[j];
#pragma unroll
        for(int kx=0;kx<7;kx++){
#pragma unroll
            for(int c=0;c<4;c++){
                float wv=ws[c*49+ky*7+kx];
#pragma unroll
                for(int p=0;p<4;p++) acc[c][p]+=r[p+kx]*wv;
            }
        }
    }
    int oy=by*16+ty, ox0=bx*64+txg*4;
#pragma unroll
    for(int c=0;c<4;c++)
        *(float4*)&g_h1[((b*4+c)<<16)+oy*256+ox0]=make_float4(acc[c][0],acc[c][1],acc[c][2],acc[c][3]);
#pragma unroll
    for(int c=0;c<4;c++){
        float s=acc[c][0]+acc[c][1]+acc[c][2]+acc[c][3];
        float q=acc[c][0]*acc[c][0]+acc[c][1]*acc[c][1]+acc[c][2]*acc[c][2]+acc[c][3]*acc[c][3];
        warp_stat(s,q,&sstat[2*c]);
    }
    __syncthreads();
    int bucket=((blockIdx.z*gridDim.y+blockIdx.y)*gridDim.x+blockIdx.x)&63;
    flush_stats(sstat,8,OFFS2,bucket);
}

// ----------------- gate (x1 * sigmoid(bn(s2))) + 2x2 maxpool -> g_p1 -----------------
__global__ void k_gate(){
    int idx=blockIdx.x*256+threadIdx.x;   // 4,194,304 threads: 2 out px each
    int ox2=idx&63, oy=(idx>>6)&127, c=(idx>>13)&3, b=idx>>15;
    float m=g_mi[OFFS2+2*c], is=g_mi[OFFS2+2*c+1];
    size_t base=((size_t)(b*4+c)<<16)+(2*oy)*256+ox2*4;
    float4 x0=*(const float4*)&g_x1[base];
    float4 x1=*(const float4*)&g_x1[base+256];
    float4 s0=*(const float4*)&g_h1[base];
    float4 s1=*(const float4*)&g_h1[base+256];
    float v[8];
    float* xp0=(float*)&x0; float* xp1=(float*)&x1;
    float* sp0=(float*)&s0; float* sp1=(float*)&s1;
#pragma unroll
    for(int j=0;j<4;j++){
        v[j]  =xp0[j]*(1.f/(1.f+expf(-(sp0[j]-m)*is)));
        v[4+j]=xp1[j]*(1.f/(1.f+expf(-(sp1[j]-m)*is)));
    }
    float o0=fmaxf(fmaxf(v[0],v[1]),fmaxf(v[4],v[5]));
    float o1=fmaxf(fmaxf(v[2],v[3]),fmaxf(v[6],v[7]));
    *(float2*)&g_p1[((b*4+c)<<14)+oy*128+2*ox2]=make_float2(o0,o1);
}

// ----------------- conv2: 4->8, 3x3, s2, p1 (zero) -----------------
__global__ void k_conv2(const float* __restrict__ w){
    __shared__ float tile[4*2210];  // 4ch x 17 x 130
    __shared__ float ws[288];
    __shared__ float sstat[16];
    int tid=threadIdx.x;
    int by=blockIdx.x, b=blockIdx.y;
    for(int i=tid;i<288;i+=256) ws[i]=w[i];
    if(tid<16) sstat[tid]=0.f;
    int iy0=by*16-1;
    for(int i=tid;i<8840;i+=256){
        int c=i/2210, j=i-c*2210;
        int r=j/130, cc=j-r*130;
        int gy=iy0+r, gx=cc-1;
        float v=0.f;
        if((unsigned)gy<128u && (unsigned)gx<128u) v=g_p1[((b*4+c)<<14)+gy*128+gx];
        tile[i]=v;
    }
    __syncthreads();
    int tx=tid&63, tyh=tid>>6;  // tyh 0..3, 2 out rows each
    float acc[8][2];
#pragma unroll
    for(int oc=0;oc<8;oc++){ acc[oc][0]=0.f; acc[oc][1]=0.f; }
    for(int c=0;c<4;c++){
#pragma unroll
        for(int ky=0;ky<3;ky++){
#pragma unroll
            for(int rr=0;rr<2;rr++){
                const float* row=&tile[c*2210+(2*(tyh*2+rr)+ky)*130+2*tx];
                float r0=row[0], r1=row[1], r2=row[2];
#pragma unroll
                for(int oc=0;oc<8;oc++){
                    const float* wp=&ws[(oc*4+c)*9+ky*3];
                    acc[oc][rr]+=r0*wp[0]+r1*wp[1]+r2*wp[2];
                }
            }
        }
    }
#pragma unroll
    for(int oc=0;oc<8;oc++){
#pragma unroll
        for(int rr=0;rr<2;rr++){
            int oy=by*8+tyh*2+rr;
            g_c2[((b*8+oc)<<12)+oy*64+tx]=acc[oc][rr];
        }
        float s=acc[oc][0]+acc[oc][1];
        float q=acc[oc][0]*acc[oc][0]+acc[oc][1]*acc[oc][1];
        warp_stat(s,q,&sstat[2*oc]);
    }
    __syncthreads();
    int bucket=(blockIdx.y*8+blockIdx.x)&63;
    flush_stats(sstat,16,OFF2,bucket);
}

// ----------------- pool + bn + relu -----------------
__global__ void k_pool2(){
    int idx=blockIdx.x*256+threadIdx.x;   // 1,048,576
    int ox=idx&31, oy=(idx>>5)&31, c=(idx>>10)&7, b=idx>>13;
    const float* p=&g_c2[((b*8+c)<<12)+(2*oy)*64+2*ox];
    float v=fmaxf(fmaxf(p[0],p[1]),fmaxf(p[64],p[65]));
    float m=g_mi[OFF2+2*c], is=g_mi[OFF2+2*c+1];
    g_p2[((b*8+c)<<10)+oy*32+ox]=fmaxf(0.f,(v-m)*is);
}
__global__ void k_pool3(){
    int idx=blockIdx.x*256+threadIdx.x;   // 524,288
    int ox=idx&15, oy=(idx>>4)&15, c=(idx>>8)&15, b=idx>>12;
    const float* p=&g_c3[((b*16+c)<<10)+(2*oy)*32+2*ox];
    float v=fmaxf(fmaxf(p[0],p[1]),fmaxf(p[32],p[33]));
    float m=g_mi[OFF3+2*c], is=g_mi[OFF3+2*c+1];
    g_p3[((b*16+c)<<8)+oy*16+ox]=fmaxf(0.f,(v-m)*is);
}

// ----------------- conv3: 8->16, 3x3, s1, p1 -----------------
__global__ void k_conv3(const float* __restrict__ w){
    __shared__ float tile[8*1156];   // 8ch x 34 x 34
    __shared__ float ws[1152];
    __shared__ float sstat[32];
    int tid=threadIdx.x, b=blockIdx.x;
    for(int i=tid;i<1152;i+=256) ws[i]=w[i];
    if(tid<32) sstat[tid]=0.f;
    for(int i=tid;i<9248;i+=256){
        int c=i/1156, j=i-c*1156;
        int r=j/34, cc=j-r*34;
        int gy=r-1, gx=cc-1;
        float v=0.f;
        if((unsigned)gy<32u && (unsigned)gx<32u) v=g_p2[((b*8+c)<<10)+gy*32+gx];
        tile[i]=v;
    }
    __syncthreads();
    int tx=tid&7, ty=tid>>3;   // 4 px along x
    float acc[16][4];
#pragma unroll
    for(int oc=0;oc<16;oc++)
#pragma unroll
        for(int p=0;p<4;p++) acc[oc][p]=0.f;
    for(int c=0;c<8;c++){
#pragma unroll
        for(int ky=0;ky<3;ky++){
            const float* row=&tile[c*1156+(ty+ky)*34+tx*4];
            float r[6];
#pragma unroll
            for(int j=0;j<6;j++) r[j]=row[j];
#pragma unroll
            for(int kx=0;kx<3;kx++){
#pragma unroll
                for(int oc=0;oc<16;oc++){
                    float wv=ws[(oc*8+c)*9+ky*3+kx];
#pragma unroll
                    for(int p=0;p<4;p++) acc[oc][p]+=r[p+kx]*wv;
                }
            }
        }
    }
#pragma unroll
    for(int oc=0;oc<16;oc++){
        *(float4*)&g_c3[((b*16+oc)<<10)+ty*32+tx*4]=make_float4(acc[oc][0],acc[oc][1],acc[oc][2],acc[oc][3]);
        float s=acc[oc][0]+acc[oc][1]+acc[oc][2]+acc[oc][3];
        float q=acc[oc][0]*acc[oc][0]+acc[oc][1]*acc[oc][1]+acc[oc][2]*acc[oc][2]+acc[oc][3]*acc[oc][3];
        warp_stat(s,q,&sstat[2*oc]);
    }
    __syncthreads();
    flush_stats(sstat,32,OFF3,b&63);
}

// ----------------- conv4: 16->32, 3x3, s1, p1 -----------------
__global__ void k_conv4(const float* __restrict__ w){
    __shared__ float tile[16*324];   // 16ch x 18 x 18
    __shared__ float ws[4608];
    __shared__ float sstat[64];
    int tid=threadIdx.x, b=blockIdx.x;
    for(int i=tid;i<4608;i+=256) ws[i]=w[i];
    if(tid<64) sstat[tid]=0.f;
    for(int i=tid;i<5184;i+=256){
        int c=i/324, j=i-c*324;
        int r=j/18, cc=j-r*18;
        int gy=r-1, gx=cc-1;
        float v=0.f;
        if((unsigned)gy<16u && (unsigned)gx<16u) v=g_p3[((b*16+c)<<8)+gy*16+gx];
        tile[i]=v;
    }
    __syncthreads();
    int tx=tid&15, ty=tid>>4;
    float acc[32];
#pragma unroll
    for(int oc=0;oc<32;oc++) acc[oc]=0.f;
    for(int c=0;c<16;c++){
#pragma unroll
        for(int ky=0;ky<3;ky++){
#pragma unroll
            for(int kx=0;kx<3;kx++){
                float v=tile[c*324+(ty+ky)*18+tx+kx];
#pragma unroll
                for(int oc=0;oc<32;oc++) acc[oc]+=v*ws[(oc*16+c)*9+ky*3+kx];
            }
        }
    }
#pragma unroll
    for(int oc=0;oc<32;oc++){
        g_c4[((b*32+oc)<<8)+tid]=acc[oc];
        warp_stat(acc[oc],acc[oc]*acc[oc],&sstat[2*oc]);
    }
    __syncthreads();
    flush_stats(sstat,64,OFF4,b&63);
}

// ----------------- conv5: 1x1, 32->16 (input = relu(bn(c4))) -----------------
__global__ void k_conv5(const float* __restrict__ w){
    __shared__ float ws[512];
    __shared__ float sstat[32];
    int tid=threadIdx.x, b=blockIdx.x;
    for(int i=tid;i<512;i+=256) ws[i]=w[i];
    if(tid<32) sstat[tid]=0.f;
    __syncthreads();
    float v[32];
#pragma unroll
    for(int c=0;c<32;c++){
        float m=g_mi[OFF4+2*c], is=g_mi[OFF4+2*c+1];
        v[c]=fmaxf(0.f,(g_c4[((b*32+c)<<8)+tid]-m)*is);
    }
#pragma unroll
    for(int oc=0;oc<16;oc++){
        float a=0.f;
#pragma unroll
        for(int c=0;c<32;c++) a+=v[c]*ws[oc*32+c];
        g_c5[((b*16+oc)<<8)+tid]=a;
        warp_stat(a,a*a,&sstat[2*oc]);
    }
    __syncthreads();
    flush_stats(sstat,32,OFF5,b&63);
}

// ----------------- mamba: both layers + residual + mean-pool, one CTA per batch -----------------
#define S_TOK   0
#define S_BUFA  4096
#define S_Z     12288
#define S_XC    20480
#define S_BM    28672
#define S_CM    32768
#define S_YS    36864
#define S_DTV   45056
#define S_W     45312
#define W_IN    (S_W+0)
#define W_WC    (S_W+1024)
#define W_CB    (S_W+1152)
#define W_XP    (S_W+1184)
#define W_DTW   (S_W+2240)
#define W_DTB   (S_W+2272)
#define W_DV    (S_W+2304)
#define W_OUT   (S_W+2336)
#define W_LNG   (S_W+2848)
#define W_LNB   (S_W+2864)
#define S_TOTAL 48192

__global__ void k_mamba(const float* __restrict__ ln_g, const float* __restrict__ ln_b,
                        const float* __restrict__ in_w, const float* __restrict__ conv_w,
                        const float* __restrict__ conv_b, const float* __restrict__ xp_w,
                        const float* __restrict__ dt_w, const float* __restrict__ dt_b,
                        const float* __restrict__ Alog, const float* __restrict__ Dv,
                        const float* __restrict__ out_w){
    extern __shared__ float sm[];
    int tid=threadIdx.x, b=blockIdx.x;
    for(int i=tid;i<4096;i+=512){
        int l=i>>4, d=i&15;
        float m=g_mi[OFF5+2*d], is=g_mi[OFF5+2*d+1];
        sm[S_TOK+i]=fmaxf(0.f,(g_c5[((b*16+d)<<8)+l]-m)*is);
    }
    __syncthreads();
    for(int layer=0;layer<2;layer++){
        for(int j=tid;j<1024;j+=512) sm[W_IN+j]=in_w[layer*1024+j];
        for(int j=tid;j<128;j+=512)  sm[W_WC+j]=conv_w[layer*128+j];
        for(int j=tid;j<1056;j+=512) sm[W_XP+j]=xp_w[layer*1056+j];
        if(tid<32){ sm[W_CB+tid]=conv_b[layer*32+tid]; sm[W_DTW+tid]=dt_w[layer*32+tid];
                    sm[W_DTB+tid]=dt_b[layer*32+tid];  sm[W_DV+tid]=Dv[layer*32+tid]; }
        for(int j=tid;j<512;j+=512) sm[W_OUT+j]=out_w[layer*512+j];
        if(tid<16){ sm[W_LNG+tid]=ln_g[layer*16+tid]; sm[W_LNB+tid]=ln_b[layer*16+tid]; }
        __syncthreads();
        {
            int l=tid>>1, half=tid&1;
            float u[16], s=0.f;
#pragma unroll
            for(int j=0;j<16;j++){ u[j]=sm[S_TOK+l*16+j]; s+=u[j]; }
            float mn=s*(1.f/16.f), vv=0.f;
#pragma unroll
            for(int j=0;j<16;j++){ float d=u[j]-mn; vv+=d*d; }
            float ist=rsqrtf(vv*(1.f/16.f)+1e-5f);
            float lnv[16];
#pragma unroll
            for(int j=0;j<16;j++) lnv[j]=(u[j]-mn)*ist*sm[W_LNG+j]+sm[W_LNB+j];
#pragma unroll
            for(int o=0;o<32;o++){
                int oc=half*32+o;
                float a=0.f;
#pragma unroll
                for(int j=0;j<16;j++) a+=lnv[j]*sm[W_IN+oc*16+j];
                if(oc<32) sm[S_BUFA+l*32+oc]=a;
                else      sm[S_Z+l*32+oc-32]=a;
            }
        }
        __syncthreads();
        for(int idx=tid;idx<8192;idx+=512){
            int l=idx>>5, d=idx&31;
            float s=sm[W_CB+d];
#pragma unroll
            for(int k=0;k<4;k++){
                int ll=l-3+k;
                if(ll>=0) s+=sm[S_BUFA+ll*32+d]*sm[W_WC+d*4+k];
            }
            sm[S_XC+idx]=s/(1.f+expf(-s));
        }
        __syncthreads();
        for(int idx=tid;idx<8448;idx+=512){
            int l=idx/33, o=idx-l*33;
            float a=0.f;
            const float* xr=&sm[S_XC+l*32];
            const float* wr=&sm[W_XP+o*32];
#pragma unroll
            for(int c=0;c<32;c++) a+=xr[c]*wr[c];
            if(o==0) sm[S_DTV+l]=a;
            else if(o<17) sm[S_BM+l*16+o-1]=a;
            else sm[S_CM+l*16+o-17]=a;
        }
        __syncthreads();
        for(int idx=tid;idx<8192;idx+=512){
            int l=idx>>5, d=idx&31;
            float xv=sm[W_DTW+d]*sm[S_DTV+l]+sm[W_DTB+d];
            sm[S_BUFA+idx]=(xv>20.f)?xv:log1pf(expf(xv));
        }
        __syncthreads();
        {
            int d=tid>>4, n=tid&15;
            float A=-expf(Alog[layer*512+d*16+n]);
            float h=0.f;
            for(int l=0;l<256;l++){
                float dl=sm[S_BUFA+l*32+d];
                float xcv=sm[S_XC+l*32+d];
                float bm=sm[S_BM+l*16+n];
                float cm=sm[S_CM+l*16+n];
                h=expf(dl*A)*h + dl*bm*xcv;
                float y=h*cm;
                y+=__shfl_xor_sync(0xffffffffu,y,1);
                y+=__shfl_xor_sync(0xffffffffu,y,2);
                y+=__shfl_xor_sync(0xffffffffu,y,4);
                y+=__shfl_xor_sync(0xffffffffu,y,8);
                if(n==0) sm[S_YS+l*32+d]=y;
            }
        }
        __syncthreads();
        for(int idx=tid;idx<8192;idx+=512){
            int d=idx&31;
            float y=sm[S_YS+idx]+sm[S_XC+idx]*sm[W_DV+d];
            float zv=sm[S_Z+idx];
            sm[S_YS+idx]=y*(zv/(1.f+expf(-zv)));
        }
        __syncthreads();
        for(int idx=tid;idx<4096;idx+=512){
            int l=idx>>4, dd=idx&15;
            float a=0.f;
            const float* gr=&sm[S_YS+l*32];
            const float* wr=&sm[W_OUT+dd*32];
#pragma unroll
            for(int d=0;d<32;d++) a+=gr[d]*wr[d];
            sm[S_TOK+idx]+=a;
        }
        __syncthreads();
    }
    if(tid<16){
        float s=0.f;
        for(int l=0;l<256;l++) s+=sm[S_TOK+l*16+tid];
        g_pool[b*16+tid]=s*(1.f/256.f);
    }
}

// ----------------- head: linear + layernorm -----------------
__global__ void k_head(const float* __restrict__ pw, const float* __restrict__ pb,
                       const float* __restrict__ fg, const float* __restrict__ fb,
                       float* __restrict__ out){
    __shared__ float pooled[16];
    __shared__ float red[256];
    int tid=threadIdx.x, b=blockIdx.x;
    if(tid<16) pooled[tid]=g_pool[b*16+tid];
    __syncthreads();
    float val=pb[tid];
#pragma unroll
    for(int j=0;j<16;j++) val+=pooled[j]*pw[tid*16+j];
    red[tid]=val;
    __syncthreads();
    for(int o=128;o>0;o>>=1){ if(tid<o) red[tid]+=red[tid+o]; __syncthreads(); }
    float m=red[0]*(1.f/256.f);
    __syncthreads();
    float d=val-m;
    red[tid]=d*d;
    __syncthreads();
    for(int o=128;o>0;o>>=1){ if(tid<o) red[tid]+=red[tid+o]; __syncthreads(); }
    float var=red[0]*(1.f/256.f);
    out[b*256+tid]=d*rsqrtf(var+1e-5f)*fg[tid]+fb[tid];
}

// ----------------- launcher -----------------
extern "C" void kernel_launch(void* const* d_in, const int* in_sizes, int n_in,
                              void* d_out, int out_size){
    const float* x    =(const float*)d_in[0];
    const float* c1_w =(const float*)d_in[1];
    const float* ca_w1=(const float*)d_in[3];
    const float* ca_b1=(const float*)d_in[4];
    const float* ca_w2=(const float*)d_in[5];
    const float* ca_b2=(const float*)d_in[6];
    const float* sa_w1=(const float*)d_in[7];
    const float* sa_w2=(const float*)d_in[8];
    const float* c2_w =(const float*)d_in[9];
    const float* c3_w =(const float*)d_in[11];
    const float* c4_w =(const float*)d_in[13];
    const float* c5_w =(const float*)d_in[15];
    const float* m_ln_g =(const float*)d_in[17];
    const float* m_ln_b =(const float*)d_in[18];
    const float* m_in_w =(const float*)d_in[19];
    const float* m_conv_w=(const float*)d_in[20];
    const float* m_conv_b=(const float*)d_in[21];
    const float* m_xp_w =(const float*)d_in[22];
    const float* m_dt_w =(const float*)d_in[23];
    const float* m_dt_b =(const float*)d_in[24];
    const float* m_Alog =(const float*)d_in[25];
    const float* m_D    =(const float*)d_in[26];
    const float* m_out_w=(const float*)d_in[27];
    const float* p_w  =(const float*)d_in[28];
    const float* p_b  =(const float*)d_in[29];
    const float* f_g  =(const float*)d_in[30];
    const float* f_b  =(const float*)d_in[31];
    float* out=(float*)d_out;

    cudaFuncSetAttribute(k_mamba, cudaFuncAttributeMaxDynamicSharedMemorySize, S_TOTAL*4);

    k_zero<<<41,256>>>();
    k_conv1<<<dim3(4,16,128),256>>>(x,c1_w);
    k_fin<<<1,32>>>(OFF1,4,1.f/8388608.f);
    k_ca<<<8192,256>>>(ca_w1,ca_b1,ca_w2,ca_b2);
    k_sa1<<<dim3(4,16,128),256>>>(sa_w1);
    k_fin<<<1,32>>>(OFFS1,1,1.f/8388608.f);
    k_sa2<<<dim3(4,16,128),256>>>(sa_w2);
    k_fin<<<1,32>>>(OFFS2,4,1.f/8388608.f);
    k_gate<<<16384,256>>>();
    k_conv2<<<dim3(8,128),256>>>(c2_w);
    k_fin<<<1,32>>>(OFF2,8,1.f/524288.f);
    k_pool2<<<4096,256>>>();
    k_conv3<<<128,256>>>(c3_w);
    k_fin<<<1,32>>>(OFF3,16,1.f/131072.f);
    k_pool3<<<2048,256>>>();
    k_conv4<<<128,256>>>(c4_w);
    k_fin<<<1,32>>>(OFF4,32,1.f/32768.f);
    k_conv5<<<128,256>>>(c5_w);
    k_fin<<<1,32>>>(OFF5,16,1.f/32768.f);
    k_mamba<<<128,512,S_TOTAL*4>>>(m_ln_g,m_ln_b,m_in_w,m_conv_w,m_conv_b,m_xp_w,
                                   m_dt_w,m_dt_b,m_Alog,m_D,m_out_w);
    k_head<<<128,256>>>(p_w,p_b,f_g,f_b,out);
}

// round 5
// speedup vs baseline: 1.0309x; 1.0309x over previous
#include <cuda_runtime.h>
#include <math.h>

#define STATW 162
#define OFF1  0
#define OFFS1 8
#define OFFS2 10
#define OFF2  18
#define OFF3  34
#define OFF4  66
#define OFF5  130

// ----------------- device scratch -----------------
__device__ float g_h1[33554432];   // conv1 raw (128,4,256,256); reused for sa2 raw
__device__ float g_x1[33554432];   // x*att
__device__ float g_s1[8388608];    // sa1 raw (128,1,256,256)
__device__ float g_p1[8388608];    // gated+pooled (128,4,128,128)
__device__ float g_c2[4194304];    // conv2 raw (128,8,64,64)
__device__ float g_p2[1048576];    // (128,8,32,32)
__device__ float g_c3[2097152];    // conv3 raw (128,16,32,32)
__device__ float g_p3[524288];     // (128,16,16,16)
__device__ float g_c4[1048576];    // conv4 raw (128,32,16,16)
__device__ float g_c5[524288];     // conv5 raw (128,16,16,16)
__device__ float g_pool[2048];     // (128,16)
__device__ float g_buckets[64*STATW];
__device__ float g_mi[STATW];      // mean/istd pairs

// ----------------- f32x2 helpers -----------------
typedef unsigned long long u64;
__device__ __forceinline__ u64 pk2(float lo,float hi){ u64 r; asm("mov.b64 %0,{%1,%2};":"=l"(r):"f"(lo),"f"(hi)); return r; }
__device__ __forceinline__ void fma2(u64& d,u64 a,u64 b){ asm("fma.rn.f32x2 %0,%1,%2,%0;":"+l"(d):"l"(a),"l"(b)); }
__device__ __forceinline__ float2 up2(u64 v){ float lo,hi; asm("mov.b64 {%0,%1},%2;":"=f"(lo),"=f"(hi):"l"(v)); return make_float2(lo,hi); }

// ----------------- helpers -----------------
__device__ __forceinline__ void warp_stat(float s, float q, float* dst){
#pragma unroll
    for (int o=16;o>0;o>>=1){ s+=__shfl_down_sync(0xffffffffu,s,o); q+=__shfl_down_sync(0xffffffffu,q,o); }
    if ((threadIdx.x&31)==0){ atomicAdd(dst,s); atomicAdd(dst+1,q); }
}
__device__ __forceinline__ void flush_stats(const float* sh, int twoC, int off, int bucket){
    for (int i=threadIdx.x;i<twoC;i+=blockDim.x) atomicAdd(&g_buckets[bucket*STATW+off+i], sh[i]);
}

__global__ void k_zero(){ int i=blockIdx.x*256+threadIdx.x; if(i<64*STATW) g_buckets[i]=0.f; }

__global__ void k_fin(int off,int C,float invN){
    int c=threadIdx.x;
    if(c<C){
        float s=0.f,q=0.f;
        for(int k=0;k<64;k++){ s+=g_buckets[k*STATW+off+2*c]; q+=g_buckets[k*STATW+off+2*c+1]; }
        float m=s*invN; float v=q*invN-m*m;
        g_mi[off+2*c]=m; g_mi[off+2*c+1]=rsqrtf(v+1e-5f);
    }
}

// ----------------- conv1: 1->4, 5x5, s2, p2 (zero) -----------------
__global__ void k_conv1(const float* __restrict__ x, const float* __restrict__ w){
    __shared__ float tile[36*132];
    __shared__ float ws[100];
    __shared__ float sstat[8];
    int tid=threadIdx.x;
    int bx=blockIdx.x, by=blockIdx.y, b=blockIdx.z;
    if (tid<100) ws[tid]=w[tid];
    if (tid<8) sstat[tid]=0.f;
    const float* xin = x + (size_t)b*262144;
    int iy0=by*32-2, ix0=bx*128-2;
    for (int i=tid;i<36*132;i+=256){
        int r=i/132, c=i-r*132;
        int gy=iy0+r, gx=ix0+c;
        float v=0.f;
        if ((unsigned)gy<512u && (unsigned)gx<512u) v=xin[gy*512+gx];
        tile[i]=v;
    }
    __syncthreads();
    int ty=tid>>4, txg=tid&15;
    float acc[4][4];
#pragma unroll
    for(int c=0;c<4;c++)
#pragma unroll
        for(int p=0;p<4;p++) acc[c][p]=0.f;
#pragma unroll
    for(int ky=0;ky<5;ky++){
        const float* row=&tile[(2*ty+ky)*132 + 8*txg];
        float r[12];
#pragma unroll
        for(int j=0;j<12;j++) r[j]=row[j];
#pragma unroll
        for(int kx=0;kx<5;kx++){
#pragma unroll
            for(int c=0;c<4;c++){
                float wv=ws[c*25+ky*5+kx];
#pragma unroll
                for(int p=0;p<4;p++) acc[c][p]+=r[2*p+kx]*wv;
            }
        }
    }
    int oy=by*16+ty, ox0=bx*64+txg*4;
#pragma unroll
    for(int c=0;c<4;c++)
        *(float4*)&g_h1[((b*4+c)<<16)+oy*256+ox0]=make_float4(acc[c][0],acc[c][1],acc[c][2],acc[c][3]);
#pragma unroll
    for(int c=0;c<4;c++){
        float s=acc[c][0]+acc[c][1]+acc[c][2]+acc[c][3];
        float q=acc[c][0]*acc[c][0]+acc[c][1]*acc[c][1]+acc[c][2]*acc[c][2]+acc[c][3]*acc[c][3];
        warp_stat(s,q,&sstat[2*c]);
    }
    __syncthreads();
    int bucket=((blockIdx.z*gridDim.y+blockIdx.y)*gridDim.x+blockIdx.x)&63;
    flush_stats(sstat,8,OFF1,bucket);
}

// ----------------- sa conv1 FUSED with bn1+relu+channel attention -----------------
// loads h1 raw, computes y=relu(bn), att, x*att -> tile + writes g_x1 (interior), then 7x7 conv -> s1
__global__ void k_sa1f(const float* __restrict__ w,
                       const float* __restrict__ w1,const float* __restrict__ b1,
                       const float* __restrict__ w2,const float* __restrict__ b2){
    __shared__ __align__(8) float tile[4*1540];   // 4ch x 22 x 70
    __shared__ __align__(8) float ws2[392];
    __shared__ float sstat[2];
    int tid=threadIdx.x;
    int bx=blockIdx.x, by=blockIdx.y, b=blockIdx.z;
    for(int i=tid;i<196;i+=256){ float v=w[i]; ws2[2*i]=v; ws2[2*i+1]=v; }
    if(tid<2) sstat[tid]=0.f;
    float m[4],is[4],W1[4],W2[4],B2[4];
#pragma unroll
    for(int c=0;c<4;c++){ m[c]=g_mi[OFF1+2*c]; is[c]=g_mi[OFF1+2*c+1]; W1[c]=w1[c]; W2[c]=w2[c]; B2[c]=b2[c]; }
    float B1=b1[0];
    int iy0=by*16-3, ix0=bx*64-3;
    for(int i=tid;i<1540;i+=256){
        int r=i/70, cc=i-r*70;
        int gy=min(max(iy0+r,0),255), gx=min(max(ix0+cc,0),255);
        int off=gy*256+gx;
        float y[4], a=B1;
#pragma unroll
        for(int c=0;c<4;c++){
            float v=g_h1[((b*4+c)<<16)+off];
            y[c]=fmaxf(0.f,(v-m[c])*is[c]);
            a+=y[c]*W1[c];
        }
        a=fmaxf(0.f,a);
        bool interior=(r>=3)&&(r<19)&&(cc>=3)&&(cc<67);
#pragma unroll
        for(int c=0;c<4;c++){
            float xv=y[c]*(a*W2[c]+B2[c]);
            tile[c*1540+i]=xv;
            if(interior) g_x1[((b*4+c)<<16)+off]=xv;
        }
    }
    __syncthreads();
    int ty=tid>>4, txg=tid&15;
    u64 acc01=pk2(0.f,0.f), acc23=pk2(0.f,0.f);
#pragma unroll
    for(int c=0;c<4;c++){
#pragma unroll
        for(int ky=0;ky<7;ky++){
            const float* row=&tile[c*1540+(ty+ky)*70+txg*4];
            float2 e0=*(const float2*)&row[0];
            float2 e1=*(const float2*)&row[2];
            float2 e2=*(const float2*)&row[4];
            float2 e3=*(const float2*)&row[6];
            float2 e4=*(const float2*)&row[8];
            u64 p[9];
            p[0]=pk2(e0.x,e0.y); p[2]=pk2(e1.x,e1.y); p[4]=pk2(e2.x,e2.y);
            p[6]=pk2(e3.x,e3.y); p[8]=pk2(e4.x,e4.y);
            p[1]=pk2(e0.y,e1.x); p[3]=pk2(e1.y,e2.x); p[5]=pk2(e2.y,e3.x); p[7]=pk2(e3.y,e4.x);
#pragma unroll
            for(int kx=0;kx<7;kx++){
                u64 wv=*(const u64*)&ws2[2*(c*49+ky*7+kx)];
                fma2(acc01,p[kx],wv);
                fma2(acc23,p[kx+2],wv);
            }
        }
    }
    float2 a01=up2(acc01), a23=up2(acc23);
    int oy=by*16+ty, ox0=bx*64+txg*4;
    *(float4*)&g_s1[(b<<16)+oy*256+ox0]=make_float4(a01.x,a01.y,a23.x,a23.y);
    float s=a01.x+a01.y+a23.x+a23.y;
    float q=a01.x*a01.x+a01.y*a01.y+a23.x*a23.x+a23.y*a23.y;
    warp_stat(s,q,&sstat[0]);
    __syncthreads();
    int bucket=((blockIdx.z*gridDim.y+blockIdx.y)*gridDim.x+blockIdx.x)&63;
    flush_stats(sstat,2,OFFS1,bucket);
}

// ----------------- sa conv2: relu(bn(s1)) -> 4ch raw (into g_h1), 7x7 edge, f32x2 -----------------
__global__ void k_sa2(const float* __restrict__ w){
    __shared__ __align__(8) float tile[1540];
    __shared__ __align__(8) float ws2[392];
    __shared__ float sstat[8];
    int tid=threadIdx.x;
    int bx=blockIdx.x, by=blockIdx.y, b=blockIdx.z;
    for(int i=tid;i<196;i+=256){ float v=w[i]; ws2[2*i]=v; ws2[2*i+1]=v; }
    if(tid<8) sstat[tid]=0.f;
    float mS=g_mi[OFFS1], iS=g_mi[OFFS1+1];
    int iy0=by*16-3, ix0=bx*64-3;
    for(int i=tid;i<1540;i+=256){
        int r=i/70, cc=i-r*70;
        int gy=min(max(iy0+r,0),255), gx=min(max(ix0+cc,0),255);
        float v=g_s1[(b<<16)+gy*256+gx];
        tile[i]=fmaxf(0.f,(v-mS)*iS);
    }
    __syncthreads();
    int ty=tid>>4, txg=tid&15;
    u64 acc[4][2];
#pragma unroll
    for(int c=0;c<4;c++){ acc[c][0]=pk2(0.f,0.f); acc[c][1]=pk2(0.f,0.f); }
#pragma unroll
    for(int ky=0;ky<7;ky++){
        const float* row=&tile[(ty+ky)*70+txg*4];
        float2 e0=*(const float2*)&row[0];
        float2 e1=*(const float2*)&row[2];
        float2 e2=*(const float2*)&row[4];
        float2 e3=*(const float2*)&row[6];
        float2 e4=*(const float2*)&row[8];
        u64 p[9];
        p[0]=pk2(e0.x,e0.y); p[2]=pk2(e1.x,e1.y); p[4]=pk2(e2.x,e2.y);
        p[6]=pk2(e3.x,e3.y); p[8]=pk2(e4.x,e4.y);
        p[1]=pk2(e0.y,e1.x); p[3]=pk2(e1.y,e2.x); p[5]=pk2(e2.y,e3.x); p[7]=pk2(e3.y,e4.x);
#pragma unroll
        for(int c=0;c<4;c++){
#pragma unroll
            for(int kx=0;kx<7;kx++){
                u64 wv=*(const u64*)&ws2[2*(c*49+ky*7+kx)];
                fma2(acc[c][0],p[kx],wv);
                fma2(acc[c][1],p[kx+2],wv);
            }
        }
    }
    int oy=by*16+ty, ox0=bx*64+txg*4;
#pragma unroll
    for(int c=0;c<4;c++){
        float2 a01=up2(acc[c][0]), a23=up2(acc[c][1]);
        *(float4*)&g_h1[((b*4+c)<<16)+oy*256+ox0]=make_float4(a01.x,a01.y,a23.x,a23.y);
        float s=a01.x+a01.y+a23.x+a23.y;
        float q=a01.x*a01.x+a01.y*a01.y+a23.x*a23.x+a23.y*a23.y;
        warp_stat(s,q,&sstat[2*c]);
    }
    __syncthreads();
    int bucket=((blockIdx.z*gridDim.y+blockIdx.y)*gridDim.x+blockIdx.x)&63;
    flush_stats(sstat,8,OFFS2,bucket);
}

// ----------------- gate (x1 * sigmoid(bn(s2))) + 2x2 maxpool -> g_p1 -----------------
__global__ void k_gate(){
    int idx=blockIdx.x*256+threadIdx.x;   // 4,194,304 threads: 2 out px each
    int ox2=idx&63, oy=(idx>>6)&127, c=(idx>>13)&3, b=idx>>15;
    float m=g_mi[OFFS2+2*c], is=g_mi[OFFS2+2*c+1];
    size_t base=((size_t)(b*4+c)<<16)+(2*oy)*256+ox2*4;
    float4 x0=*(const float4*)&g_x1[base];
    float4 x1=*(const float4*)&g_x1[base+256];
    float4 s0=*(const float4*)&g_h1[base];
    float4 s1=*(const float4*)&g_h1[base+256];
    float v[8];
    float* xp0=(float*)&x0; float* xp1=(float*)&x1;
    float* sp0=(float*)&s0; float* sp1=(float*)&s1;
#pragma unroll
    for(int j=0;j<4;j++){
        v[j]  =xp0[j]*(1.f/(1.f+expf(-(sp0[j]-m)*is)));
        v[4+j]=xp1[j]*(1.f/(1.f+expf(-(sp1[j]-m)*is)));
    }
    float o0=fmaxf(fmaxf(v[0],v[1]),fmaxf(v[4],v[5]));
    float o1=fmaxf(fmaxf(v[2],v[3]),fmaxf(v[6],v[7]));
    *(float2*)&g_p1[((b*4+c)<<14)+oy*128+2*ox2]=make_float2(o0,o1);
}

// ----------------- conv2: 4->8, 3x3, s2, p1 (zero) -----------------
__global__ void k_conv2(const float* __restrict__ w){
    __shared__ float tile[4*2210];  // 4ch x 17 x 130
    __shared__ float ws[288];
    __shared__ float sstat[16];
    int tid=threadIdx.x;
    int by=blockIdx.x, b=blockIdx.y;
    for(int i=tid;i<288;i+=256) ws[i]=w[i];
    if(tid<16) sstat[tid]=0.f;
    int iy0=by*16-1;
    for(int i=tid;i<8840;i+=256){
        int c=i/2210, j=i-c*2210;
        int r=j/130, cc=j-r*130;
        int gy=iy0+r, gx=cc-1;
        float v=0.f;
        if((unsigned)gy<128u && (unsigned)gx<128u) v=g_p1[((b*4+c)<<14)+gy*128+gx];
        tile[i]=v;
    }
    __syncthreads();
    int tx=tid&63, tyh=tid>>6;  // tyh 0..3, 2 out rows each
    float acc[8][2];
#pragma unroll
    for(int oc=0;oc<8;oc++){ acc[oc][0]=0.f; acc[oc][1]=0.f; }
    for(int c=0;c<4;c++){
#pragma unroll
        for(int ky=0;ky<3;ky++){
#pragma unroll
            for(int rr=0;rr<2;rr++){
                const float* row=&tile[c*2210+(2*(tyh*2+rr)+ky)*130+2*tx];
                float r0=row[0], r1=row[1], r2=row[2];
#pragma unroll
                for(int oc=0;oc<8;oc++){
                    const float* wp=&ws[(oc*4+c)*9+ky*3];
                    acc[oc][rr]+=r0*wp[0]+r1*wp[1]+r2*wp[2];
                }
            }
        }
    }
#pragma unroll
    for(int oc=0;oc<8;oc++){
#pragma unroll
        for(int rr=0;rr<2;rr++){
            int oy=by*8+tyh*2+rr;
            g_c2[((b*8+oc)<<12)+oy*64+tx]=acc[oc][rr];
        }
        float s=acc[oc][0]+acc[oc][1];
        float q=acc[oc][0]*acc[oc][0]+acc[oc][1]*acc[oc][1];
        warp_stat(s,q,&sstat[2*oc]);
    }
    __syncthreads();
    int bucket=(blockIdx.y*8+blockIdx.x)&63;
    flush_stats(sstat,16,OFF2,bucket);
}

// ----------------- pool + bn + relu -----------------
__global__ void k_pool2(){
    int idx=blockIdx.x*256+threadIdx.x;   // 1,048,576
    int ox=idx&31, oy=(idx>>5)&31, c=(idx>>10)&7, b=idx>>13;
    const float* p=&g_c2[((b*8+c)<<12)+(2*oy)*64+2*ox];
    float v=fmaxf(fmaxf(p[0],p[1]),fmaxf(p[64],p[65]));
    float m=g_mi[OFF2+2*c], is=g_mi[OFF2+2*c+1];
    g_p2[((b*8+c)<<10)+oy*32+ox]=fmaxf(0.f,(v-m)*is);
}
__global__ void k_pool3(){
    int idx=blockIdx.x*256+threadIdx.x;   // 524,288
    int ox=idx&15, oy=(idx>>4)&15, c=(idx>>8)&15, b=idx>>12;
    const float* p=&g_c3[((b*16+c)<<10)+(2*oy)*32+2*ox];
    float v=fmaxf(fmaxf(p[0],p[1]),fmaxf(p[32],p[33]));
    float m=g_mi[OFF3+2*c], is=g_mi[OFF3+2*c+1];
    g_p3[((b*16+c)<<8)+oy*16+ox]=fmaxf(0.f,(v-m)*is);
}

// ----------------- conv3: 8->16, 3x3, s1, p1 -----------------
__global__ void k_conv3(const float* __restrict__ w){
    __shared__ float tile[8*1156];   // 8ch x 34 x 34
    __shared__ float ws[1152];
    __shared__ float sstat[32];
    int tid=threadIdx.x, b=blockIdx.x;
    for(int i=tid;i<1152;i+=256) ws[i]=w[i];
    if(tid<32) sstat[tid]=0.f;
    for(int i=tid;i<9248;i+=256){
        int c=i/1156, j=i-c*1156;
        int r=j/34, cc=j-r*34;
        int gy=r-1, gx=cc-1;
        float v=0.f;
        if((unsigned)gy<32u && (unsigned)gx<32u) v=g_p2[((b*8+c)<<10)+gy*32+gx];
        tile[i]=v;
    }
    __syncthreads();
    int tx=tid&7, ty=tid>>3;   // 4 px along x
    float acc[16][4];
#pragma unroll
    for(int oc=0;oc<16;oc++)
#pragma unroll
        for(int p=0;p<4;p++) acc[oc][p]=0.f;
    for(int c=0;c<8;c++){
#pragma unroll
        for(int ky=0;ky<3;ky++){
            const float* row=&tile[c*1156+(ty+ky)*34+tx*4];
            float r[6];
#pragma unroll
            for(int j=0;j<6;j++) r[j]=row[j];
#pragma unroll
            for(int kx=0;kx<3;kx++){
#pragma unroll
                for(int oc=0;oc<16;oc++){
                    float wv=ws[(oc*8+c)*9+ky*3+kx];
#pragma unroll
                    for(int p=0;p<4;p++) acc[oc][p]+=r[p+kx]*wv;
                }
            }
        }
    }
#pragma unroll
    for(int oc=0;oc<16;oc++){
        *(float4*)&g_c3[((b*16+oc)<<10)+ty*32+tx*4]=make_float4(acc[oc][0],acc[oc][1],acc[oc][2],acc[oc][3]);
        float s=acc[oc][0]+acc[oc][1]+acc[oc][2]+acc[oc][3];
        float q=acc[oc][0]*acc[oc][0]+acc[oc][1]*acc[oc][1]+acc[oc][2]*acc[oc][2]+acc[oc][3]*acc[oc][3];
        warp_stat(s,q,&sstat[2*oc]);
    }
    __syncthreads();
    flush_stats(sstat,32,OFF3,b&63);
}

// ----------------- conv4: 16->32, 3x3, s1, p1 -----------------
__global__ void k_conv4(const float* __restrict__ w){
    __shared__ float tile[16*324];   // 16ch x 18 x 18
    __shared__ float ws[4608];
    __shared__ float sstat[64];
    int tid=threadIdx.x, b=blockIdx.x;
    for(int i=tid;i<4608;i+=256) ws[i]=w[i];
    if(tid<64) sstat[tid]=0.f;
    for(int i=tid;i<5184;i+=256){
        int c=i/324, j=i-c*324;
        int r=j/18, cc=j-r*18;
        int gy=r-1, gx=cc-1;
        float v=0.f;
        if((unsigned)gy<16u && (unsigned)gx<16u) v=g_p3[((b*16+c)<<8)+gy*16+gx];
        tile[i]=v;
    }
    __syncthreads();
    int tx=tid&15, ty=tid>>4;
    float acc[32];
#pragma unroll
    for(int oc=0;oc<32;oc++) acc[oc]=0.f;
    for(int c=0;c<16;c++){
#pragma unroll
        for(int ky=0;ky<3;ky++){
#pragma unroll
            for(int kx=0;kx<3;kx++){
                float v=tile[c*324+(ty+ky)*18+tx+kx];
#pragma unroll
                for(int oc=0;oc<32;oc++) acc[oc]+=v*ws[(oc*16+c)*9+ky*3+kx];
            }
        }
    }
#pragma unroll
    for(int oc=0;oc<32;oc++){
        g_c4[((b*32+oc)<<8)+tid]=acc[oc];
        warp_stat(acc[oc],acc[oc]*acc[oc],&sstat[2*oc]);
    }
    __syncthreads();
    flush_stats(sstat,64,OFF4,b&63);
}

// ----------------- conv5: 1x1, 32->16 (input = relu(bn(c4))) -----------------
__global__ void k_conv5(const float* __restrict__ w){
    __shared__ float ws[512];
    __shared__ float sstat[32];
    int tid=threadIdx.x, b=blockIdx.x;
    for(int i=tid;i<512;i+=256) ws[i]=w[i];
    if(tid<32) sstat[tid]=0.f;
    __syncthreads();
    float v[32];
#pragma unroll
    for(int c=0;c<32;c++){
        float m=g_mi[OFF4+2*c], is=g_mi[OFF4+2*c+1];
        v[c]=fmaxf(0.f,(g_c4[((b*32+c)<<8)+tid]-m)*is);
    }
#pragma unroll
    for(int oc=0;oc<16;oc++){
        float a=0.f;
#pragma unroll
        for(int c=0;c<32;c++) a+=v[c]*ws[oc*32+c];
        g_c5[((b*16+oc)<<8)+tid]=a;
        warp_stat(a,a*a,&sstat[2*oc]);
    }
    __syncthreads();
    flush_stats(sstat,32,OFF5,b&63);
}

// ----------------- mamba: both layers + residual + mean-pool, one CTA per batch -----------------
#define S_TOK   0
#define S_BUFA  4096
#define S_Z     12288
#define S_XC    20480
#define S_BM    28672
#define S_CM    32768
#define S_YS    36864
#define S_DTV   45056
#define S_W     45312
#define W_IN    (S_W+0)
#define W_WC    (S_W+1024)
#define W_CB    (S_W+1152)
#define W_XP    (S_W+1184)
#define W_DTW   (S_W+2240)
#define W_DTB   (S_W+2272)
#define W_DV    (S_W+2304)
#define W_OUT   (S_W+2336)
#define W_LNG   (S_W+2848)
#define W_LNB   (S_W+2864)
#define S_TOTAL 48192

__global__ void k_mamba(const float* __restrict__ ln_g, const float* __restrict__ ln_b,
                        const float* __restrict__ in_w, const float* __restrict__ conv_w,
                        const float* __restrict__ conv_b, const float* __restrict__ xp_w,
                        const float* __restrict__ dt_w, const float* __restrict__ dt_b,
                        const float* __restrict__ Alog, const float* __restrict__ Dv,
                        const float* __restrict__ out_w){
    extern __shared__ float sm[];
    int tid=threadIdx.x, b=blockIdx.x;
    for(int i=tid;i<4096;i+=512){
        int l=i>>4, d=i&15;
        float m=g_mi[OFF5+2*d], is=g_mi[OFF5+2*d+1];
        sm[S_TOK+i]=fmaxf(0.f,(g_c5[((b*16+d)<<8)+l]-m)*is);
    }
    __syncthreads();
    for(int layer=0;layer<2;layer++){
        for(int j=tid;j<1024;j+=512) sm[W_IN+j]=in_w[layer*1024+j];
        for(int j=tid;j<128;j+=512)  sm[W_WC+j]=conv_w[layer*128+j];
        for(int j=tid;j<1056;j+=512) sm[W_XP+j]=xp_w[layer*1056+j];
        if(tid<32){ sm[W_CB+tid]=conv_b[layer*32+tid]; sm[W_DTW+tid]=dt_w[layer*32+tid];
                    sm[W_DTB+tid]=dt_b[layer*32+tid];  sm[W_DV+tid]=Dv[layer*32+tid]; }
        for(int j=tid;j<512;j+=512) sm[W_OUT+j]=out_w[layer*512+j];
        if(tid<16){ sm[W_LNG+tid]=ln_g[layer*16+tid]; sm[W_LNB+tid]=ln_b[layer*16+tid]; }
        __syncthreads();
        {
            int l=tid>>1, half=tid&1;
            float u[16], s=0.f;
#pragma unroll
            for(int j=0;j<16;j++){ u[j]=sm[S_TOK+l*16+j]; s+=u[j]; }
            float mn=s*(1.f/16.f), vv=0.f;
#pragma unroll
            for(int j=0;j<16;j++){ float d=u[j]-mn; vv+=d*d; }
            float ist=rsqrtf(vv*(1.f/16.f)+1e-5f);
            float lnv[16];
#pragma unroll
            for(int j=0;j<16;j++) lnv[j]=(u[j]-mn)*ist*sm[W_LNG+j]+sm[W_LNB+j];
#pragma unroll
            for(int o=0;o<32;o++){
                int oc=half*32+o;
                float a=0.f;
#pragma unroll
                for(int j=0;j<16;j++) a+=lnv[j]*sm[W_IN+oc*16+j];
                if(oc<32) sm[S_BUFA+l*32+oc]=a;
                else      sm[S_Z+l*32+oc-32]=a;
            }
        }
        __syncthreads();
        for(int idx=tid;idx<8192;idx+=512){
            int l=idx>>5, d=idx&31;
            float s=sm[W_CB+d];
#pragma unroll
            for(int k=0;k<4;k++){
                int ll=l-3+k;
                if(ll>=0) s+=sm[S_BUFA+ll*32+d]*sm[W_WC+d*4+k];
            }
            sm[S_XC+idx]=s/(1.f+expf(-s));
        }
        __syncthreads();
        for(int idx=tid;idx<8448;idx+=512){
            int l=idx/33, o=idx-l*33;
            float a=0.f;
            const float* xr=&sm[S_XC+l*32];
            const float* wr=&sm[W_XP+o*32];
#pragma unroll
            for(int c=0;c<32;c++) a+=xr[c]*wr[c];
            if(o==0) sm[S_DTV+l]=a;
            else if(o<17) sm[S_BM+l*16+o-1]=a;
            else sm[S_CM+l*16+o-17]=a;
        }
        __syncthreads();
        for(int idx=tid;idx<8192;idx+=512){
            int l=idx>>5, d=idx&31;
            float xv=sm[W_DTW+d]*sm[S_DTV+l]+sm[W_DTB+d];
            sm[S_BUFA+idx]=(xv>20.f)?xv:log1pf(expf(xv));
        }
        __syncthreads();
        {
            int d=tid>>4, n=tid&15;
            float A=-expf(Alog[layer*512+d*16+n]);
            float h=0.f;
            for(int l=0;l<256;l++){
                float dl=sm[S_BUFA+l*32+d];
                float xcv=sm[S_XC+l*32+d];
                float bm=sm[S_BM+l*16+n];
                float cm=sm[S_CM+l*16+n];
                h=expf(dl*A)*h + dl*bm*xcv;
                float y=h*cm;
                y+=__shfl_xor_sync(0xffffffffu,y,1);
                y+=__shfl_xor_sync(0xffffffffu,y,2);
                y+=__shfl_xor_sync(0xffffffffu,y,4);
                y+=__shfl_xor_sync(0xffffffffu,y,8);
                if(n==0) sm[S_YS+l*32+d]=y;
            }
        }
        __syncthreads();
        for(int idx=tid;idx<8192;idx+=512){
            int d=idx&31;
            float y=sm[S_YS+idx]+sm[S_XC+idx]*sm[W_DV+d];
            float zv=sm[S_Z+idx];
            sm[S_YS+idx]=y*(zv/(1.f+expf(-zv)));
        }
        __syncthreads();
        for(int idx=tid;idx<4096;idx+=512){
            int l=idx>>4, dd=idx&15;
            float a=0.f;
            const float* gr=&sm[S_YS+l*32];
            const float* wr=&sm[W_OUT+dd*32];
#pragma unroll
            for(int d=0;d<32;d++) a+=gr[d]*wr[d];
            sm[S_TOK+idx]+=a;
        }
        __syncthreads();
    }
    if(tid<16){
        float s=0.f;
        for(int l=0;l<256;l++) s+=sm[S_TOK+l*16+tid];
        g_pool[b*16+tid]=s*(1.f/256.f);
    }
}

// ----------------- head: linear + layernorm -----------------
__global__ void k_head(const float* __restrict__ pw, const float* __restrict__ pb,
                       const float* __restrict__ fg, const float* __restrict__ fb,
                       float* __restrict__ out){
    __shared__ float pooled[16];
    __shared__ float red[256];
    int tid=threadIdx.x, b=blockIdx.x;
    if(tid<16) pooled[tid]=g_pool[b*16+tid];
    __syncthreads();
    float val=pb[tid];
#pragma unroll
    for(int j=0;j<16;j++) val+=pooled[j]*pw[tid*16+j];
    red[tid]=val;
    __syncthreads();
    for(int o=128;o>0;o>>=1){ if(tid<o) red[tid]+=red[tid+o]; __syncthreads(); }
    float m=red[0]*(1.f/256.f);
    __syncthreads();
    float d=val-m;
    red[tid]=d*d;
    __syncthreads();
    for(int o=128;o>0;o>>=1){ if(tid<o) red[tid]+=red[tid+o]; __syncthreads(); }
    float var=red[0]*(1.f/256.f);
    out[b*256+tid]=d*rsqrtf(var+1e-5f)*fg[tid]+fb[tid];
}

// ----------------- launcher -----------------
extern "C" void kernel_launch(void* const* d_in, const int* in_sizes, int n_in,
                              void* d_out, int out_size){
    const float* x    =(const float*)d_in[0];
    const float* c1_w =(const float*)d_in[1];
    const float* ca_w1=(const float*)d_in[3];
    const float* ca_b1=(const float*)d_in[4];
    const float* ca_w2=(const float*)d_in[5];
    const float* ca_b2=(const float*)d_in[6];
    const float* sa_w1=(const float*)d_in[7];
    const float* sa_w2=(const float*)d_in[8];
    const float* c2_w =(const float*)d_in[9];
    const float* c3_w =(const float*)d_in[11];
    const float* c4_w =(const float*)d_in[13];
    const float* c5_w =(const float*)d_in[15];
    const float* m_ln_g =(const float*)d_in[17];
    const float* m_ln_b =(const float*)d_in[18];
    const float* m_in_w =(const float*)d_in[19];
    const float* m_conv_w=(const float*)d_in[20];
    const float* m_conv_b=(const float*)d_in[21];
    const float* m_xp_w =(const float*)d_in[22];
    const float* m_dt_w =(const float*)d_in[23];
    const float* m_dt_b =(const float*)d_in[24];
    const float* m_Alog =(const float*)d_in[25];
    const float* m_D    =(const float*)d_in[26];
    const float* m_out_w=(const float*)d_in[27];
    const float* p_w  =(const float*)d_in[28];
    const float* p_b  =(const float*)d_in[29];
    const float* f_g  =(const float*)d_in[30];
    const float* f_b  =(const float*)d_in[31];
    float* out=(float*)d_out;

    cudaFuncSetAttribute(k_mamba, cudaFuncAttributeMaxDynamicSharedMemorySize, S_TOTAL*4);

    k_zero<<<41,256>>>();
    k_conv1<<<dim3(4,16,128),256>>>(x,c1_w);
    k_fin<<<1,32>>>(OFF1,4,1.f/8388608.f);
    k_sa1f<<<dim3(4,16,128),256>>>(sa_w1,ca_w1,ca_b1,ca_w2,ca_b2);
    k_fin<<<1,32>>>(OFFS1,1,1.f/8388608.f);
    k_sa2<<<dim3(4,16,128),256>>>(sa_w2);
    k_fin<<<1,32>>>(OFFS2,4,1.f/8388608.f);
    k_gate<<<16384,256>>>();
    k_conv2<<<dim3(8,128),256>>>(c2_w);
    k_fin<<<1,32>>>(OFF2,8,1.f/524288.f);
    k_pool2<<<4096,256>>>();
    k_conv3<<<128,256>>>(c3_w);
    k_fin<<<1,32>>>(OFF3,16,1.f/131072.f);
    k_pool3<<<2048,256>>>();
    k_conv4<<<128,256>>>(c4_w);
    k_fin<<<1,32>>>(OFF4,32,1.f/32768.f);
    k_conv5<<<128,256>>>(c5_w);
    k_fin<<<1,32>>>(OFF5,16,1.f/32768.f);
    k_mamba<<<128,512,S_TOTAL*4>>>(m_ln_g,m_ln_b,m_in_w,m_conv_w,m_conv_b,m_xp_w,
                                   m_dt_w,m_dt_b,m_Alog,m_D,m_out_w);
    k_head<<<128,256>>>(p_w,p_b,f_g,f_b,out);
}